// round 5
// baseline (speedup 1.0000x reference)
#include <cuda_runtime.h>

#define NPOS 2304          // 48*48
#define PPAD 2916          // 54*54
typedef unsigned long long ull;

// Scratch (device globals; no runtime allocation)
__device__ float Qbuf[2 * 4 * 2304 * 64];   // [b][g][p][c64]
__device__ float Kbuf[2 * 8 * 2916 * 32];   // [b][SL][padded pos][c32]  (borders never read)
__device__ float Vbuf[2 * 4 * 2916 * 64];   // [b][g][padded pos][c64]  (borders never read)

// ---------------------------------------------------------------------------
// f32x2 helpers
// ---------------------------------------------------------------------------
__device__ __forceinline__ ull dup2(float a) {
    ull r;
    asm("mov.b64 %0, {%1, %1};" : "=l"(r) : "f"(a));
    return r;
}
__device__ __forceinline__ void fma2(ull& d, ull a, ull b) {
    asm("fma.rn.f32x2 %0, %1, %2, %0;" : "+l"(d) : "l"(a), "l"(b));
}

// ---------------------------------------------------------------------------
// Kernel 1: 1x1 conv GEMM, FFMA2, conflict-free smem, software-pipelined LDG.
// C[768,2304] = W[768,256] * X[256,2304] per batch.
// Tile 128(o) x 64(n), 256 threads, microtile 8(o, f32x2 pairs) x 4(n).
// ---------------------------------------------------------------------------
__global__ __launch_bounds__(256, 3) void conv_kernel(const float* __restrict__ x,
                                                      const float* __restrict__ w) {
    __shared__ float As[16][128];   // [k][o]
    __shared__ float Bs[16][64];    // [k][n]

    const int b  = blockIdx.z;
    const int o0 = blockIdx.y * 128;
    const int n0 = blockIdx.x * 64;
    const int t  = threadIdx.x;
    const int ty = t & 15;      // o quad index
    const int tx = t >> 4;      // n quad index

    const float* Xb = x + b * (256 * NPOS);

    ull acc[4][4];
#pragma unroll
    for (int i = 0; i < 4; i++)
#pragma unroll
        for (int j = 0; j < 4; j++) acc[i][j] = 0ull;

    const int ao0 = t >> 2, akq = t & 3;          // A loader rep 0
    const int ao1 = (t + 256) >> 2;               // A loader rep 1 (same akq)
    const int bkk = t >> 4, bn4 = t & 15;         // B loader

    // Preload first k-slab
    float4 av0 = *(const float4*)(w + (o0 + ao0) * 256 + akq * 4);
    float4 av1 = *(const float4*)(w + (o0 + ao1) * 256 + akq * 4);
    float4 bv  = *(const float4*)(Xb + bkk * NPOS + n0 + bn4 * 4);

    for (int c0 = 0; c0 < 256; c0 += 16) {
        __syncthreads();
        As[akq * 4 + 0][ao0] = av0.x;
        As[akq * 4 + 1][ao0] = av0.y;
        As[akq * 4 + 2][ao0] = av0.z;
        As[akq * 4 + 3][ao0] = av0.w;
        As[akq * 4 + 0][ao1] = av1.x;
        As[akq * 4 + 1][ao1] = av1.y;
        As[akq * 4 + 2][ao1] = av1.z;
        As[akq * 4 + 3][ao1] = av1.w;
        *(float4*)&Bs[bkk][bn4 * 4] = bv;
        __syncthreads();

        if (c0 + 16 < 256) {   // prefetch next slab (hidden under compute)
            av0 = *(const float4*)(w + (o0 + ao0) * 256 + c0 + 16 + akq * 4);
            av1 = *(const float4*)(w + (o0 + ao1) * 256 + c0 + 16 + akq * 4);
            bv  = *(const float4*)(Xb + (c0 + 16 + bkk) * NPOS + n0 + bn4 * 4);
        }

#pragma unroll
        for (int kk = 0; kk < 16; kk++) {
            ull ap[4];
            *(float4*)(&ap[0]) = *(const float4*)&As[kk][ty * 4];
            *(float4*)(&ap[2]) = *(const float4*)&As[kk][64 + ty * 4];
            float bb[4];
            *(float4*)bb = *(const float4*)&Bs[kk][tx * 4];
            ull bd0 = dup2(bb[0]), bd1 = dup2(bb[1]), bd2 = dup2(bb[2]), bd3 = dup2(bb[3]);
#pragma unroll
            for (int op = 0; op < 4; op++) {
                fma2(acc[op][0], ap[op], bd0);
                fma2(acc[op][1], ap[op], bd1);
                fma2(acc[op][2], ap[op], bd2);
                fma2(acc[op][3], ap[op], bd3);
            }
        }
    }

    // Epilogue: smem-free, channel-contiguous STG.128 (coalesced in ty).
#pragma unroll
    for (int nj = 0; nj < 4; nj++) {
        int hw = n0 + tx * 4 + nj;
        unsigned uhw = (unsigned)hw;
        int i2 = uhw / 48u, j2 = uhw - 48u * i2;
        int pp = (i2 + 3) * 54 + (j2 + 3);
#pragma unroll
        for (int half = 0; half < 2; half++) {
            float2 p0 = *(float2*)&acc[half * 2 + 0][nj];
            float2 p1 = *(float2*)&acc[half * 2 + 1][nj];
            float4 v = make_float4(p0.x, p0.y, p1.x, p1.y);
            int o = o0 + half * 64 + ty * 4;
            if (o < 256) {
                int g = o >> 6;
                *(float4*)&Qbuf[(((b * 4 + g) * 2304 + hw) << 6) + (o & 63)] = v;
            } else if (o < 512) {
                int ok = o - 256;
                int SL = ((ok >> 5) & 1) * 4 + (ok >> 6);
                *(float4*)&Kbuf[(((b * 8 + SL) * PPAD + pp) << 5) + (ok & 31)] = v;
            } else {
                int ov = o - 512;
                *(float4*)&Vbuf[(((b * 4 + (ov >> 6)) * PPAD + pp) << 6) + (ov & 63)] = v;
            }
        }
    }
}

// ---------------------------------------------------------------------------
// Kernel 2: attention, shuffle-free QK. One block per (b, g, row i').
// 384 threads; lane sub of each 8-lane position group owns k = sub + 8*i.
// K staged with 9-float4 cell stride (anti-conflict padding).
// ---------------------------------------------------------------------------
__device__ __forceinline__ float red8(float v) {
    v += __shfl_xor_sync(0xffffffffu, v, 1);
    v += __shfl_xor_sync(0xffffffffu, v, 2);
    v += __shfl_xor_sync(0xffffffffu, v, 4);
    return v;
}
__device__ __forceinline__ float max8(float v) {
    v = fmaxf(v, __shfl_xor_sync(0xffffffffu, v, 1));
    v = fmaxf(v, __shfl_xor_sync(0xffffffffu, v, 2));
    v = fmaxf(v, __shfl_xor_sync(0xffffffffu, v, 4));
    return v;
}
__device__ __forceinline__ float dot4(float4 a, float4 b) {
    return a.x * b.x + a.y * b.y + a.z * b.z + a.w * b.w;
}

#define KT_SRC_F4 3456    // 8*54*8
#define KT_DST_F4 3888    // 8*54*9 (padded cells)
#define VT_F4 6048        // 7*54*16
#define ATT_STRIDE 52

__global__ __launch_bounds__(384, 1) void attn_kernel(const float* __restrict__ rpeh,
                                                      const float* __restrict__ rpew,
                                                      float* __restrict__ out) {
    extern __shared__ float sm[];
    float* Kt   = sm;                       // 15552 floats (padded cells)
    float* Vt   = sm + 15552;               // 24192 floats
    float* atts = Vt + 24192;               // 48*52
    float* rtab = atts + 48 * ATT_STRIDE;   // 48*16

    const int ip = blockIdx.x;
    const int g  = blockIdx.y;
    const int b  = blockIdx.z;
    const int t  = threadIdx.x;

    const int s_ = (ip >= 24) ? 1 : 0;
    const int SL = 2 * g + s_;
    const int R0 = 2 * ip - 48 * s_;

    const float4 z4 = make_float4(0.f, 0.f, 0.f, 0.f);

    // ---- Stage K (remapped to padded stride) and V; zero-fill borders ----
    {
        const float4* ks = (const float4*)(Kbuf + (((b * 8 + SL) * PPAD + R0 * 54) << 5));
        float4* kt4 = (float4*)Kt;
        for (int i = t; i < KT_SRC_F4; i += 384) {
            int cell = i >> 3, c4 = i & 7;
            unsigned lr = (unsigned)cell / 54u, col = (unsigned)cell - 54u * lr;
            unsigned grow = (unsigned)R0 + lr;
            bool inter = (grow - 3u) < 48u && (col - 3u) < 48u;
            kt4[cell * 9 + c4] = inter ? ks[i] : z4;
        }
        const float4* vsrc = (const float4*)(Vbuf + (((b * 4 + g) * PPAD + ip * 54) << 6));
        float4* vt4 = (float4*)Vt;
        for (int i = t; i < VT_F4; i += 384) {
            unsigned pl = (unsigned)(i >> 4);
            unsigned lr = pl / 54u, col = pl - 54u * lr;
            unsigned grow = (unsigned)ip + lr;
            bool inter = (grow - 3u) < 48u && (col - 3u) < 48u;
            vt4[i] = inter ? vsrc[i] : z4;
        }
    }

    const int pos = t >> 3;
    const int sub = t & 7;

    // ---- q into registers as f32x2 pairs (pair p = channels 2p,2p+1) ----
    const float* qp = Qbuf + (((b * 4 + g) * 2304 + ip * 48 + pos) << 6);
    ull ql[16], qh[16];
#pragma unroll
    for (int c4 = 0; c4 < 8; c4++) {
        float4 v = *(const float4*)(qp + 4 * c4);
        ql[2 * c4]     = *(ull*)&v.x;
        ql[2 * c4 + 1] = *(ull*)&v.z;
        float4 u = *(const float4*)(qp + 32 + 4 * c4);
        qh[2 * c4]     = *(ull*)&u.x;
        qh[2 * c4 + 1] = *(ull*)&u.z;
    }

    // ---- RPE table -> smem (lane 0 of each group writes) ----
    const bool useH = (SL < 4);
    {
        const float4 qlo4 = *(const float4*)(qp + 4 * sub);
        const float4 qhi4 = *(const float4*)(qp + 32 + 4 * sub);
        const float* rp = useH ? (rpeh + SL * 224) : (rpew + (SL - 4) * 224);
        float Rlo[7], Rhi[7];
#pragma unroll
        for (int tt = 0; tt < 7; tt++) {
            float4 rv = *(const float4*)(rp + tt * 32 + 4 * sub);
            Rlo[tt] = red8(dot4(qlo4, rv));
            Rhi[tt] = red8(dot4(qhi4, rv));
        }
        if (sub == 0) {
#pragma unroll
            for (int tt = 0; tt < 7; tt++) {
                rtab[pos * 16 + tt]     = Rlo[tt];
                rtab[pos * 16 + 8 + tt] = Rhi[tt];
            }
        }
    }

    __syncthreads();

    const int rsel = (pos >= 24) ? 1 : 0;
    const int j0 = 2 * pos - 48 * rsel;

    // ---- QK: lane sub computes logits for k = sub + 8*it ----
    float Lreg[7];
    const float4* kt4 = (const float4*)Kt;
#pragma unroll
    for (int it = 0; it < 7; it++) {
        int k = sub + 8 * it;
        bool live = (k < 49);
        int kc = live ? k : 0;
        int wA, wB, rA, rB;
        if (kc < 24)       { wA = 2 * kc;      rA = 0; wB = 2 * kc + 1;  rB = 0; }
        else if (kc == 24) { wA = 48;          rA = 0; wB = 0;           rB = 1; }
        else               { wA = 2 * kc - 49; rA = 1; wB = 2 * kc - 48; rB = 1; }
        unsigned khA = (unsigned)wA / 7u, kwA = (unsigned)wA - 7u * khA;
        unsigned khB = (unsigned)wB / 7u, kwB = (unsigned)wB - 7u * khB;
        const float4* pA = kt4 + ((rsel + khA) * 54 + j0 + rA + kwA) * 9;
        const float4* pB = kt4 + ((rsel + khB) * 54 + j0 + rB + kwB) * 9;
        ull accA = 0ull, accB = 0ull;
#pragma unroll
        for (int c4 = 0; c4 < 8; c4++) {
            float4 ka = pA[c4];
            fma2(accA, *(ull*)&ka.x, ql[2 * c4]);
            fma2(accA, *(ull*)&ka.z, ql[2 * c4 + 1]);
            float4 kb = pB[c4];
            fma2(accB, *(ull*)&kb.x, qh[2 * c4]);
            fma2(accB, *(ull*)&kb.z, qh[2 * c4 + 1]);
        }
        float2 sa = *(float2*)&accA;
        float2 sb = *(float2*)&accB;
        int idxA = useH ? (int)khA : (int)kwA;
        int idxB = useH ? (int)khB : (int)kwB;
        float radd = rtab[pos * 16 + idxA] + rtab[pos * 16 + 8 + idxB];
        Lreg[it] = live ? (sa.x + sa.y + sb.x + sb.y + radd) : -1e30f;
    }

    // ---- softmax across the 8 lanes (k distributed) ----
    float m = Lreg[0];
#pragma unroll
    for (int i = 1; i < 7; i++) m = fmaxf(m, Lreg[i]);
    m = max8(m);
    float ssum = 0.f;
#pragma unroll
    for (int i = 0; i < 7; i++) { Lreg[i] = __expf(Lreg[i] - m); ssum += Lreg[i]; }
    ssum = red8(ssum);
    float inv = 1.0f / ssum;
#pragma unroll
    for (int i = 0; i < 7; i++) {
        int k = sub + 8 * i;
        if (k < 49) atts[pos * ATT_STRIDE + k] = Lreg[i] * inv;
    }
    __syncwarp();

    // ---- AV (f32x2): lane accumulates channels {4sub..} and {32+4sub..} ----
    ull a0[2] = {0ull, 0ull}, a1[2] = {0ull, 0ull};
    const float4* vt4 = (const float4*)Vt;
#pragma unroll
    for (int k = 0; k < 49; k++) {
        const int kh = k / 7, kw = k % 7;
        float a = atts[pos * ATT_STRIDE + k];
        ull ad = dup2(a);
        const float4* vv = vt4 + (((kh * 54 + pos + kw) << 4) + sub);
        float4 v0 = vv[0];
        float4 v1 = vv[8];
        fma2(a0[0], ad, *(ull*)&v0.x);
        fma2(a0[1], ad, *(ull*)&v0.z);
        fma2(a1[0], ad, *(ull*)&v1.x);
        fma2(a1[1], ad, *(ull*)&v1.z);
    }
    float4 acc0 = *(float4*)&a0[0];
    float4 acc1 = *(float4*)&a1[0];

    float* op = out + (b * 256 + g * 64) * NPOS + ip * 48 + pos;
    op[(4 * sub + 0) * NPOS] = acc0.x;
    op[(4 * sub + 1) * NPOS] = acc0.y;
    op[(4 * sub + 2) * NPOS] = acc0.z;
    op[(4 * sub + 3) * NPOS] = acc0.w;
    op[(32 + 4 * sub + 0) * NPOS] = acc1.x;
    op[(32 + 4 * sub + 1) * NPOS] = acc1.y;
    op[(32 + 4 * sub + 2) * NPOS] = acc1.z;
    op[(32 + 4 * sub + 3) * NPOS] = acc1.w;
}

// ---------------------------------------------------------------------------
extern "C" void kernel_launch(void* const* d_in, const int* in_sizes, int n_in,
                              void* d_out, int out_size) {
    const float* x  = (const float*)d_in[0];
    const float* w  = (const float*)d_in[1];
    const float* rh = (const float*)d_in[2];
    const float* rw = (const float*)d_in[3];
    float* out = (float*)d_out;

    dim3 gc(36, 6, 2);   // n=2304/64, o=768/128, b
    conv_kernel<<<gc, 256>>>(x, w);

    const int SMEM = (15552 + 24192 + 48 * ATT_STRIDE + 48 * 16) * 4;
    cudaFuncSetAttribute(attn_kernel, cudaFuncAttributeMaxDynamicSharedMemorySize, SMEM);
    dim3 ga(48, 4, 2);
    attn_kernel<<<ga, 384, SMEM>>>(rh, rw, out);
}

// round 6
// speedup vs baseline: 1.1188x; 1.1188x over previous
#include <cuda_runtime.h>

#define NPOS 2304          // 48*48
#define PPAD 2916          // 54*54
typedef unsigned long long ull;

// Scratch (device globals; no runtime allocation)
__device__ float Qbuf[2 * 4 * 2304 * 64];   // [b][g][p][c64]
__device__ float Kbuf[2 * 8 * 2916 * 32];   // [b][SL][padded pos][c32]  (borders never read)
__device__ float Vbuf[2 * 4 * 2916 * 64];   // [b][g][padded pos][c64]  (borders never read)

// ---------------------------------------------------------------------------
// f32x2 helpers
// ---------------------------------------------------------------------------
__device__ __forceinline__ ull dup2(float a) {
    ull r;
    asm("mov.b64 %0, {%1, %1};" : "=l"(r) : "f"(a));
    return r;
}
__device__ __forceinline__ void fma2(ull& d, ull a, ull b) {
    asm("fma.rn.f32x2 %0, %1, %2, %0;" : "+l"(d) : "l"(a), "l"(b));
}

// ---------------------------------------------------------------------------
// Kernel 1: 1x1 conv GEMM, FFMA2, conflict-free smem, software-pipelined LDG.
// Tile 128(o) x 64(n), 256 threads, microtile 8(o, f32x2 pairs) x 4(n).
// ---------------------------------------------------------------------------
__global__ __launch_bounds__(256, 3) void conv_kernel(const float* __restrict__ x,
                                                      const float* __restrict__ w) {
    __shared__ float As[16][128];   // [k][o]
    __shared__ float Bs[16][64];    // [k][n]

    const int b  = blockIdx.z;
    const int o0 = blockIdx.y * 128;
    const int n0 = blockIdx.x * 64;
    const int t  = threadIdx.x;
    const int ty = t & 15;      // o quad index
    const int tx = t >> 4;      // n quad index

    const float* Xb = x + b * (256 * NPOS);

    ull acc[4][4];
#pragma unroll
    for (int i = 0; i < 4; i++)
#pragma unroll
        for (int j = 0; j < 4; j++) acc[i][j] = 0ull;

    const int ao0 = t >> 2, akq = t & 3;
    const int ao1 = (t + 256) >> 2;
    const int bkk = t >> 4, bn4 = t & 15;

    float4 av0 = *(const float4*)(w + (o0 + ao0) * 256 + akq * 4);
    float4 av1 = *(const float4*)(w + (o0 + ao1) * 256 + akq * 4);
    float4 bv  = *(const float4*)(Xb + bkk * NPOS + n0 + bn4 * 4);

    for (int c0 = 0; c0 < 256; c0 += 16) {
        __syncthreads();
        As[akq * 4 + 0][ao0] = av0.x;
        As[akq * 4 + 1][ao0] = av0.y;
        As[akq * 4 + 2][ao0] = av0.z;
        As[akq * 4 + 3][ao0] = av0.w;
        As[akq * 4 + 0][ao1] = av1.x;
        As[akq * 4 + 1][ao1] = av1.y;
        As[akq * 4 + 2][ao1] = av1.z;
        As[akq * 4 + 3][ao1] = av1.w;
        *(float4*)&Bs[bkk][bn4 * 4] = bv;
        __syncthreads();

        if (c0 + 16 < 256) {
            av0 = *(const float4*)(w + (o0 + ao0) * 256 + c0 + 16 + akq * 4);
            av1 = *(const float4*)(w + (o0 + ao1) * 256 + c0 + 16 + akq * 4);
            bv  = *(const float4*)(Xb + (c0 + 16 + bkk) * NPOS + n0 + bn4 * 4);
        }

#pragma unroll
        for (int kk = 0; kk < 16; kk++) {
            ull ap[4];
            *(float4*)(&ap[0]) = *(const float4*)&As[kk][ty * 4];
            *(float4*)(&ap[2]) = *(const float4*)&As[kk][64 + ty * 4];
            float bb[4];
            *(float4*)bb = *(const float4*)&Bs[kk][tx * 4];
            ull bd0 = dup2(bb[0]), bd1 = dup2(bb[1]), bd2 = dup2(bb[2]), bd3 = dup2(bb[3]);
#pragma unroll
            for (int op = 0; op < 4; op++) {
                fma2(acc[op][0], ap[op], bd0);
                fma2(acc[op][1], ap[op], bd1);
                fma2(acc[op][2], ap[op], bd2);
                fma2(acc[op][3], ap[op], bd3);
            }
        }
    }

#pragma unroll
    for (int nj = 0; nj < 4; nj++) {
        int hw = n0 + tx * 4 + nj;
        unsigned uhw = (unsigned)hw;
        int i2 = uhw / 48u, j2 = uhw - 48u * i2;
        int pp = (i2 + 3) * 54 + (j2 + 3);
#pragma unroll
        for (int half = 0; half < 2; half++) {
            float2 p0 = *(float2*)&acc[half * 2 + 0][nj];
            float2 p1 = *(float2*)&acc[half * 2 + 1][nj];
            float4 v = make_float4(p0.x, p0.y, p1.x, p1.y);
            int o = o0 + half * 64 + ty * 4;
            if (o < 256) {
                int g = o >> 6;
                *(float4*)&Qbuf[(((b * 4 + g) * 2304 + hw) << 6) + (o & 63)] = v;
            } else if (o < 512) {
                int ok = o - 256;
                int SL = ((ok >> 5) & 1) * 4 + (ok >> 6);
                *(float4*)&Kbuf[(((b * 8 + SL) * PPAD + pp) << 5) + (ok & 31)] = v;
            } else {
                int ov = o - 512;
                *(float4*)&Vbuf[(((b * 4 + (ov >> 6)) * PPAD + pp) << 6) + (ov & 63)] = v;
            }
        }
    }
}

// ---------------------------------------------------------------------------
// Kernel 2: attention, round-4 inner structure, TWO output rows per block.
// 768 threads: rh = t/384 selects row (ip0+rh); within row: pos = tt>>3 (j'),
// sub = tt&7 (4-channel slice lane). 192 blocks total (1.3 waves).
// ---------------------------------------------------------------------------
__device__ __forceinline__ float red8(float v) {
    v += __shfl_xor_sync(0xffffffffu, v, 1);
    v += __shfl_xor_sync(0xffffffffu, v, 2);
    v += __shfl_xor_sync(0xffffffffu, v, 4);
    return v;
}
__device__ __forceinline__ float max8(float v) {
    v = fmaxf(v, __shfl_xor_sync(0xffffffffu, v, 1));
    v = fmaxf(v, __shfl_xor_sync(0xffffffffu, v, 2));
    v = fmaxf(v, __shfl_xor_sync(0xffffffffu, v, 4));
    return v;
}
__device__ __forceinline__ float dot4(float4 a, float4 b) {
    return a.x * b.x + a.y * b.y + a.z * b.z + a.w * b.w;
}

#define KT_F4 4320    // 10*54*8
#define VT_F4 6912    // 8*54*16
#define ATT_STRIDE 52

__global__ __launch_bounds__(768, 1) void attn_kernel(const float* __restrict__ rpeh,
                                                      const float* __restrict__ rpew,
                                                      float* __restrict__ out) {
    extern __shared__ float sm[];
    float* Kt   = sm;                        // 17280 floats (10 rows x 54 x 32)
    float* Vt   = sm + 17280;                // 27648 floats (8 rows x 54 x 64)
    float* atts = Vt + 27648;                // 96*52
    float* rtab = atts + 96 * ATT_STRIDE;    // 96*16

    const int ip0 = blockIdx.x * 2;  // first output row of this block
    const int g   = blockIdx.y;
    const int b   = blockIdx.z;
    const int t   = threadIdx.x;

    const int s_  = (ip0 >= 24) ? 1 : 0;     // same for ip0 and ip0+1 (ip0 even)
    const int SL  = 2 * g + s_;
    const int R0  = 2 * ip0 - 48 * s_;       // K tile base row (10 rows staged)

    const float4 z4 = make_float4(0.f, 0.f, 0.f, 0.f);

    // ---- Stage K rows R0..R0+9 and V rows ip0..ip0+7; zero-fill borders ----
    {
        const float4* ks = (const float4*)(Kbuf + (((b * 8 + SL) * PPAD + R0 * 54) << 5));
        float4* kt4 = (float4*)Kt;
        for (int i = t; i < KT_F4; i += 768) {
            unsigned pl = (unsigned)(i >> 3);
            unsigned lr = pl / 54u, col = pl - 54u * lr;
            unsigned grow = (unsigned)R0 + lr;
            bool inter = (grow - 3u) < 48u && (col - 3u) < 48u;
            kt4[i] = inter ? ks[i] : z4;
        }
        const float4* vsrc = (const float4*)(Vbuf + (((b * 4 + g) * PPAD + ip0 * 54) << 6));
        float4* vt4 = (float4*)Vt;
        for (int i = t; i < VT_F4; i += 768) {
            unsigned pl = (unsigned)(i >> 4);
            unsigned lr = pl / 54u, col = pl - 54u * lr;
            unsigned grow = (unsigned)ip0 + lr;
            bool inter = (grow - 3u) < 48u && (col - 3u) < 48u;
            vt4[i] = inter ? vsrc[i] : z4;
        }
    }

    const int rh  = t >> 9 ? 1 : (t >= 384 ? 1 : 0);   // row half (t/384)
    const int tt  = t - rh * 384;
    const int ip  = ip0 + rh;
    const int pos = tt >> 3;   // j' 0..47
    const int sub = tt & 7;
    const int pidx = rh * 48 + pos;   // position slot in atts/rtab

    // q slices (coalesced gmem)
    const float* qp = Qbuf + (((b * 4 + g) * 2304 + ip * 48 + pos) << 6);
    const float4 qlo = *(const float4*)(qp + 4 * sub);
    const float4 qhi = *(const float4*)(qp + 32 + 4 * sub);

    // RPE dot products -> rtab
    const bool useH = (SL < 4);
    const float* rp = useH ? (rpeh + SL * 224) : (rpew + (SL - 4) * 224);
    {
        float Rlo[7], Rhi[7];
#pragma unroll
        for (int tq = 0; tq < 7; tq++) {
            float4 rv = *(const float4*)(rp + tq * 32 + 4 * sub);
            Rlo[tq] = red8(dot4(qlo, rv));
            Rhi[tq] = red8(dot4(qhi, rv));
        }
        if (sub == 0) {
#pragma unroll
            for (int tq = 0; tq < 7; tq++) {
                rtab[pidx * 16 + tq]     = Rlo[tq];
                rtab[pidx * 16 + 8 + tq] = Rhi[tq];
            }
        }
    }

    __syncthreads();

    const int rsel = (pos >= 24) ? 1 : 0;
    const int j0 = 2 * pos - 48 * rsel;
    const int krow0 = 2 * rh + rsel;     // base row within 10-row K tile

    float Lreg[7] = {0.f, 0.f, 0.f, 0.f, 0.f, 0.f, 0.f};

    const float4* kt4 = (const float4*)Kt;
#pragma unroll
    for (int k = 0; k < 49; k++) {
        int wA, wB, rA, rB;
        if (k < 24)       { wA = 2 * k;      rA = 0; wB = 2 * k + 1;  rB = 0; }
        else if (k == 24) { wA = 48;         rA = 0; wB = 0;          rB = 1; }
        else              { wA = 2 * k - 49; rA = 1; wB = 2 * k - 48; rB = 1; }
        const int khA = wA / 7, kwA = wA % 7;
        const int khB = wB / 7, kwB = wB % 7;
        float4 va = kt4[(((krow0 + khA) * 54 + j0 + rA + kwA) << 3) + sub];
        float4 vb = kt4[(((krow0 + khB) * 54 + j0 + rB + kwB) << 3) + sub];
        float p = dot4(qlo, va) + dot4(qhi, vb);
        p = red8(p);
        float radd = useH ? (rtab[pidx * 16 + khA] + rtab[pidx * 16 + 8 + khB])
                          : (rtab[pidx * 16 + kwA] + rtab[pidx * 16 + 8 + kwB]);
        float L = p + radd;
        if ((k & 7) == sub) Lreg[k >> 3] = L;
    }

    // softmax over 49 (k distributed across the 8 lanes)
    const int nk = (sub == 0) ? 7 : 6;
    float m = -1e30f;
#pragma unroll
    for (int i = 0; i < 7; i++)
        if (i < nk) m = fmaxf(m, Lreg[i]);
    m = max8(m);
    float ssum = 0.f;
#pragma unroll
    for (int i = 0; i < 7; i++)
        if (i < nk) { Lreg[i] = __expf(Lreg[i] - m); ssum += Lreg[i]; }
    ssum = red8(ssum);
    float inv = 1.0f / ssum;
#pragma unroll
    for (int i = 0; i < 7; i++) {
        int k = sub + 8 * i;
        if (k < 49) atts[pidx * ATT_STRIDE + k] = Lreg[i] * inv;
    }
    __syncwarp();

    // AV (f32x2): lane accumulates channels {4sub..} and {32+4sub..}
    ull a0[2] = {0ull, 0ull}, a1[2] = {0ull, 0ull};
    const float4* vt4 = (const float4*)Vt;
#pragma unroll
    for (int k = 0; k < 49; k++) {
        const int kh = k / 7, kw = k % 7;
        float a = atts[pidx * ATT_STRIDE + k];
        ull ad = dup2(a);
        const float4* vv = vt4 + ((((rh + kh) * 54 + pos + kw) << 4) + sub);
        float4 v0 = vv[0];
        float4 v1 = vv[8];
        fma2(a0[0], ad, *(ull*)&v0.x);
        fma2(a0[1], ad, *(ull*)&v0.z);
        fma2(a1[0], ad, *(ull*)&v1.x);
        fma2(a1[1], ad, *(ull*)&v1.z);
    }
    float4 acc0 = *(float4*)&a0[0];
    float4 acc1 = *(float4*)&a1[0];

    float* op = out + (b * 256 + g * 64) * NPOS + ip * 48 + pos;
    op[(4 * sub + 0) * NPOS] = acc0.x;
    op[(4 * sub + 1) * NPOS] = acc0.y;
    op[(4 * sub + 2) * NPOS] = acc0.z;
    op[(4 * sub + 3) * NPOS] = acc0.w;
    op[(32 + 4 * sub + 0) * NPOS] = acc1.x;
    op[(32 + 4 * sub + 1) * NPOS] = acc1.y;
    op[(32 + 4 * sub + 2) * NPOS] = acc1.z;
    op[(32 + 4 * sub + 3) * NPOS] = acc1.w;
}

// ---------------------------------------------------------------------------
extern "C" void kernel_launch(void* const* d_in, const int* in_sizes, int n_in,
                              void* d_out, int out_size) {
    const float* x  = (const float*)d_in[0];
    const float* w  = (const float*)d_in[1];
    const float* rh = (const float*)d_in[2];
    const float* rw = (const float*)d_in[3];
    float* out = (float*)d_out;

    dim3 gc(36, 6, 2);   // n=2304/64, o=768/128, b
    conv_kernel<<<gc, 256>>>(x, w);

    const int SMEM = (17280 + 27648 + 96 * ATT_STRIDE + 96 * 16) * 4;
    cudaFuncSetAttribute(attn_kernel, cudaFuncAttributeMaxDynamicSharedMemorySize, SMEM);
    dim3 ga(24, 4, 2);   // 2 rows per block
    attn_kernel<<<ga, 768, SMEM>>>(rh, rw, out);
}